// round 5
// baseline (speedup 1.0000x reference)
#include <cuda_runtime.h>
#include <cstdint>

typedef unsigned long long ull;

// Problem: x (8,256,128,128) f32 -> out (8,256,64,64) f32
// CARAFE downsample: 1x1 conv(256->64) . 3x3 s2 conv(64->25) . softmax . 5x5 s2 gather

#define RF       72          // padded floats per staged row
#define RQ       18          // float4 chunks per row
// logits: tile 32w x 8h, region 17 rows, 2 channels/stage
#define L_ROWS   17
#define L_CHF    1224        // 17*72 floats per channel
#define L_FLOATS 2448        // per stage
#define L_CHUNKS 612
#define L_SLOTS  5
// aggregate: tile 32w x 8h, region 19 rows, 2 channels/stage
#define A_ROWS   19
#define A_CHF    1368        // 19*72
#define A_FLOATS 2736
#define A_CHUNKS 684
#define A_SLOTS  6

// ---- persistent device scratch ----
__device__ float4 g_W2[128 * 9 * 13];        // [cp][tap][kk]{w2k_c0,w2k_c1,w2k1_c0,w2k1_c1}
__device__ float  g_btap[9 * 32];            // per-tap bias (b_comp through encoder)
__device__ float  g_bk[32];                  // b_enc * exp(p)
__device__ float  g_part[8 * 25 * 64 * 64];  // raw logit sums

__device__ __forceinline__ ull pack2(float a, float b) {
    ull r; asm("mov.b64 %0, {%1, %2};" : "=l"(r) : "f"(a), "f"(b)); return r;
}
__device__ __forceinline__ void unpack2(ull v, float& a, float& b) {
    asm("mov.b64 {%0, %1}, %2;" : "=f"(a), "=f"(b) : "l"(v));
}
#define FMA2(d, a, b) asm("fma.rn.f32x2 %0, %1, %2, %0;" : "+l"(d) : "l"(a), "l"(b))

__device__ __forceinline__ uint32_t smem_u32(const void* p) {
    return (uint32_t)__cvta_generic_to_shared(p);
}
__device__ __forceinline__ void cpa16(uint32_t dst, const void* src) {
    asm volatile("cp.async.ca.shared.global [%0], [%1], 16;" :: "r"(dst), "l"(src));
}
#define CP_COMMIT() asm volatile("cp.async.commit_group;")
template<int N> __device__ __forceinline__ void cp_wait() {
    asm volatile("cp.async.wait_group %0;" :: "n"(N));
}

// ============================================================================
// Kernel 1: fuse compressor+encoder weights. 9 blocks (tap) x 256 threads (c).
// ============================================================================
__global__ void prep_kernel(const float* __restrict__ w_comp, const float* __restrict__ b_comp,
                            const float* __restrict__ w_enc, const float* __restrict__ b_enc,
                            const float* __restrict__ power_p) {
    int tap = blockIdx.x;
    int c   = threadIdx.x;
    __shared__ float we[25][64];
    __shared__ float bc[64];
    float expP = __expf(power_p[0]);
    for (int i = c; i < 1600; i += 256) {
        int k = i >> 6, cc = i & 63;
        we[k][cc] = w_enc[(k * 64 + cc) * 9 + tap];
    }
    if (c < 64) bc[c] = b_comp[c];
    __syncthreads();

    float wc[64];
#pragma unroll
    for (int cc = 0; cc < 64; cc++) wc[cc] = w_comp[cc * 256 + c];

    float* W2f = (float*)g_W2;
    int cp = c >> 1, lane = c & 1;
#pragma unroll 1
    for (int k = 0; k < 25; k++) {
        float s = 0.f;
#pragma unroll
        for (int cc = 0; cc < 64; cc++) s += we[k][cc] * wc[cc];
        s *= expP;
        W2f[((cp * 9 + tap) * 13 + (k >> 1)) * 4 + (k & 1) * 2 + lane] = s;
    }
    if (c < 128) {  // zero k=25 pad lanes
        W2f[((c * 9 + tap) * 13 + 12) * 4 + 2] = 0.f;
        W2f[((c * 9 + tap) * 13 + 12) * 4 + 3] = 0.f;
    }
    if (c < 25) {
        float bs = 0.f;
        for (int cc = 0; cc < 64; cc++) bs += we[c][cc] * bc[cc];
        g_btap[tap * 32 + c] = bs * expP;
        if (tap == 0) g_bk[c] = b_enc[c] * expP;
    }
}

// ============================================================================
// Kernel 2: fused 3x3-s2 logit conv. 128 blocks (8b x 16 tiles of 32w x 8h),
// 128 threads, 2 px/thread, channel-pair f32x2, 3-stage coalesced cp.async.
// ============================================================================
__global__ __launch_bounds__(128, 2) void logits_kernel(const float* __restrict__ x) {
    int bid  = blockIdx.x;
    int b    = bid >> 4;
    int tile = bid & 15;
    int w0 = (tile & 1) * 32;
    int h0 = (tile >> 1) * 8;
    int tid = threadIdx.x;
    int lw = tid & 31;
    int lh = tid >> 5;

    __shared__ __align__(16) float raw[3][L_FLOATS];  // [ch0 plane | ch1 plane], rows of 72
    __shared__ float4 ws[3][117];

    for (int i = tid; i < 3 * L_FLOATS; i += 128) ((float*)raw)[i] = 0.f;

    // one-time slot addressing (chunk = 16B of one gmem row)
    int goff[L_SLOTS];
    unsigned vmask = 0;
#pragma unroll
    for (int j = 0; j < L_SLOTS; j++) {
        int idx = tid + j * 128;
        int ch = 0, row = 0, col = 0;
        bool ok = idx < L_CHUNKS;
        if (ok) {
            ch = idx / 306; int rem = idx - ch * 306;
            int r = rem / RQ, q = rem - r * RQ;
            row = 2 * h0 - 1 + r;
            col = 2 * w0 - 4 + 4 * q;
            ok = (row >= 0) && (col >= 0) && (col <= 124);
        }
        if (ok) vmask |= 1u << j;
        goff[j] = ch * 16384 + row * 128 + col;
    }
    uint32_t rawb = smem_u32(&raw[0][0]) + (uint32_t)tid * 16;
    uint32_t wsb  = smem_u32(&ws[0][0])  + (uint32_t)tid * 16;
    const float* xb = x + (size_t)b * 256 * 16384;

    auto fill = [&](int s, int cp) {
        const float* xc = xb + (size_t)(2 * cp) * 16384;
        uint32_t d = rawb + (uint32_t)s * (L_FLOATS * 4);
#pragma unroll
        for (int j = 0; j < L_SLOTS; j++)
            if (vmask & (1u << j)) cpa16(d + j * 2048, xc + goff[j]);
        if (tid < 117) cpa16(wsb + (uint32_t)s * (117 * 16), &g_W2[cp * 117 + tid]);
    };

    ull acc0[26], acc1[26];
#pragma unroll
    for (int i = 0; i < 26; i++) { acc0[i] = 0ull; acc1[i] = 0ull; }

    __syncthreads();
    fill(0, 0); CP_COMMIT();
    fill(1, 1); CP_COMMIT();
#pragma unroll 1
    for (int i = 0; i < 128; i++) {
        int s = i % 3;
        __syncthreads();                       // prior consume done before refilling its stage
        if (i + 2 < 128) fill((i + 2) % 3, i + 2);
        CP_COMMIT();                           // group i+2 (possibly empty)
        cp_wait<2>();                          // group i complete
        __syncthreads();                       // cross-thread visibility

        const float* rp = &raw[s][0];
#pragma unroll
        for (int dy = 0; dy < 3; dy++) {
#pragma unroll
            for (int dx = 0; dx < 3; dx++) {
                int tap = dy * 3 + dx;
                int ccol = 2 * lw + dx + 3;
                const float* pA = rp + (2 * lh + dy) * RF + ccol;
                const float* pB = rp + (2 * lh + 8 + dy) * RF + ccol;
                ull xv0 = pack2(pA[0], pA[L_CHF]);
                ull xv1 = pack2(pB[0], pB[L_CHF]);
                const ulonglong2* wp = (const ulonglong2*)(&ws[s][tap * 13]);
#pragma unroll
                for (int kk = 0; kk < 13; kk++) {
                    ulonglong2 wv = wp[kk];
                    FMA2(acc0[2 * kk],     wv.x, xv0);
                    FMA2(acc0[2 * kk + 1], wv.y, xv0);
                    FMA2(acc1[2 * kk],     wv.x, xv1);
                    FMA2(acc1[2 * kk + 1], wv.y, xv1);
                }
            }
        }
    }

    // store raw logit sums
    int w = w0 + lw, hA = h0 + lh, hB = hA + 4;
#pragma unroll
    for (int k = 0; k < 25; k++) {
        float a, c2;
        unpack2(acc0[k], a, c2);
        g_part[((b * 25 + k) << 12) + (hA << 6) + w] = a + c2;
        unpack2(acc1[k], a, c2);
        g_part[((b * 25 + k) << 12) + (hB << 6) + w] = a + c2;
    }
}

// ============================================================================
// Kernel 3: softmax prologue + 25-tap s2 gather. 128 blocks (8b x 16 tiles of
// 32w x 8h), 128 threads, 2 px/thread, spatial-pair f32x2 (clean LDS.64 from
// raw layout), 3-stage coalesced cp.async.
// ============================================================================
__global__ __launch_bounds__(128, 2) void aggregate_kernel(const float* __restrict__ x,
                                                           float* __restrict__ out) {
    int bid  = blockIdx.x;
    int b    = bid >> 4;
    int tile = bid & 15;
    int w0 = (tile & 1) * 32;
    int h0 = (tile >> 1) * 8;
    int tid = threadIdx.x;
    int lw = tid & 31;
    int lh = tid >> 5;
    int w = w0 + lw;

    __shared__ __align__(16) float raw[3][A_FLOATS];
    __shared__ float btap_s[288];
    __shared__ float bk_s[32];

    for (int i = tid; i < 288; i += 128) btap_s[i] = g_btap[i];
    if (tid < 32) bk_s[tid] = g_bk[tid];
    for (int i = tid; i < 3 * A_FLOATS; i += 128) ((float*)raw)[i] = 0.f;

    int goff[A_SLOTS];
    unsigned vmask = 0;
#pragma unroll
    for (int j = 0; j < A_SLOTS; j++) {
        int idx = tid + j * 128;
        int ch = 0, row = 0, col = 0;
        bool ok = idx < A_CHUNKS;
        if (ok) {
            ch = idx / 342; int rem = idx - ch * 342;
            int r = rem / RQ, q = rem - r * RQ;
            row = 2 * h0 - 2 + r;
            col = 2 * w0 - 4 + 4 * q;
            ok = (row >= 0) && (row < 128) && (col >= 0) && (col <= 124);
        }
        if (ok) vmask |= 1u << j;
        goff[j] = ch * 16384 + row * 128 + col;
    }
    uint32_t rawb = smem_u32(&raw[0][0]) + (uint32_t)tid * 16;
    const float* xb = x + (size_t)b * 256 * 16384;

    __syncthreads();

    // softmax prologue -> packed spatial mask pairs  mp[px][di][j]
    ull mp[2][5][3];
#pragma unroll
    for (int px = 0; px < 2; px++) {
        int h = h0 + lh + 4 * px;
        float logit[25];
        size_t base = (size_t)((b * 25) << 12) + (h << 6) + w;
#pragma unroll
        for (int k = 0; k < 25; k++) logit[k] = g_part[base + (k << 12)] + bk_s[k];
#pragma unroll
        for (int tap = 0; tap < 9; tap++) {
            int dy = tap / 3, dx = tap % 3;
            bool inb = (2 * h - 1 + dy >= 0) && (2 * w - 1 + dx >= 0) && (2 * w - 1 + dx < 128);
            if (inb) {
#pragma unroll
                for (int k = 0; k < 25; k++) logit[k] += btap_s[tap * 32 + k];
            }
        }
        float mx = logit[0];
#pragma unroll
        for (int k = 1; k < 25; k++) mx = fmaxf(mx, logit[k]);
        float sum = 0.f;
#pragma unroll
        for (int k = 0; k < 25; k++) { logit[k] = __expf(logit[k] - mx); sum += logit[k]; }
        float inv = 1.f / sum;
#pragma unroll
        for (int k = 0; k < 25; k++) logit[k] *= inv;
#pragma unroll
        for (int di = 0; di < 5; di++) {
            mp[px][di][0] = pack2(logit[5 * di],     logit[5 * di + 1]);
            mp[px][di][1] = pack2(logit[5 * di + 2], logit[5 * di + 3]);
            mp[px][di][2] = pack2(logit[5 * di + 4], 0.f);
        }
    }

    auto fill = [&](int s, int cp) {
        const float* xc = xb + (size_t)(2 * cp) * 16384;
        uint32_t d = rawb + (uint32_t)s * (A_FLOATS * 4);
#pragma unroll
        for (int j = 0; j < A_SLOTS; j++)
            if (vmask & (1u << j)) cpa16(d + j * 2048, xc + goff[j]);
    };

    float* ob = out + (((size_t)b * 256) << 12) + w;
    fill(0, 0); CP_COMMIT();
    fill(1, 1); CP_COMMIT();
#pragma unroll 1
    for (int i = 0; i < 128; i++) {
        int s = i % 3;
        __syncthreads();
        if (i + 2 < 128) fill((i + 2) % 3, i + 2);
        CP_COMMIT();
        cp_wait<2>();
        __syncthreads();

        const float* rp = &raw[s][0];
        ull acc[2][2] = {{0ull, 0ull}, {0ull, 0ull}};   // [ch][px]
#pragma unroll
        for (int di = 0; di < 5; di++) {
#pragma unroll
            for (int px = 0; px < 2; px++) {
                int lr = 2 * lh + di + 8 * px;
                const float* rowp = rp + lr * RF + 2 * lw + 2;
                ull x0 = *(const ull*)(rowp);
                ull x1 = *(const ull*)(rowp + 2);
                ull x2 = *(const ull*)(rowp + 4);
                FMA2(acc[0][px], mp[px][di][0], x0);
                FMA2(acc[0][px], mp[px][di][1], x1);
                FMA2(acc[0][px], mp[px][di][2], x2);
                ull y0 = *(const ull*)(rowp + A_CHF);
                ull y1 = *(const ull*)(rowp + A_CHF + 2);
                ull y2 = *(const ull*)(rowp + A_CHF + 4);
                FMA2(acc[1][px], mp[px][di][0], y0);
                FMA2(acc[1][px], mp[px][di][1], y1);
                FMA2(acc[1][px], mp[px][di][2], y2);
            }
        }
#pragma unroll
        for (int ch = 0; ch < 2; ch++) {
#pragma unroll
            for (int px = 0; px < 2; px++) {
                float a, c2;
                unpack2(acc[ch][px], a, c2);
                ob[(((size_t)(2 * i + ch)) << 12) + ((h0 + lh + 4 * px) << 6)] = a + c2;
            }
        }
    }
}

// ============================================================================
extern "C" void kernel_launch(void* const* d_in, const int* in_sizes, int n_in,
                              void* d_out, int out_size) {
    const float* x       = (const float*)d_in[0];
    const float* w_comp  = (const float*)d_in[1];
    const float* b_comp  = (const float*)d_in[2];
    const float* w_enc   = (const float*)d_in[3];
    const float* b_enc   = (const float*)d_in[4];
    const float* power_p = (const float*)d_in[5];
    float* out = (float*)d_out;

    prep_kernel<<<9, 256>>>(w_comp, b_comp, w_enc, b_enc, power_p);
    logits_kernel<<<128, 128>>>(x);
    aggregate_kernel<<<128, 128>>>(x, out);
}